// round 13
// baseline (speedup 1.0000x reference)
#include <cuda_runtime.h>
#include <cuda_bf16.h>
#include <math.h>
#include <stdint.h>

#define Bdim 8192
#define Edim 4096
#define DEMB 256
#define HIDD 1024
#define DIS 128
#define SYM 512
#define DST 640   // DIS + SYM

enum { ACT_NONE = 0, ACT_RELU = 1, ACT_FSIG = 2, ACT_FINAL = 3 };
enum { OUT_F32 = 0, OUT_SPLIT = 1, OUT_SPLIT_T = 2 };
enum { A_PRE = 0, A_EXACT = 1, A_F32 = 2 };

typedef __nv_bfloat16 bf16;

// ---------------- scratch layout ----------------
constexpr size_t N_ST   = (size_t)Bdim * DEMB;
constexpr size_t N_H1   = (size_t)Bdim * HIDD;
constexpr size_t N_DIS  = (size_t)Bdim * DIS;
constexpr size_t N_SYMM = (size_t)Bdim * SYM;
constexpr size_t N_STU  = (size_t)Bdim * DST;
constexpr size_t N_WG   = (size_t)Edim * DEMB;
constexpr size_t N_GR   = (size_t)Edim * DEMB;
constexpr size_t N_WD1  = (size_t)SYM * DIS;
constexpr size_t N_W1   = (size_t)DEMB * HIDD;
constexpr size_t N_W2   = (size_t)HIDD * SYM;
constexpr size_t N_WM1  = (size_t)DST * HIDD;
constexpr size_t N_MD   = (size_t)DIS * SYM;

constexpr size_t O_ST_H  = 0;
constexpr size_t O_ST_M  = O_ST_H  + N_ST;
constexpr size_t O_H1_H  = O_ST_M  + N_ST;
constexpr size_t O_H1_M  = O_H1_H  + N_H1;
constexpr size_t O_DIS_H = O_H1_M  + N_H1;
constexpr size_t O_DIS_M = O_DIS_H + N_DIS;
constexpr size_t O_SYMM  = O_DIS_M + N_DIS;
constexpr size_t O_STU   = O_SYMM  + N_SYMM;
constexpr size_t O_WG_H  = O_STU   + N_STU;   // W_g^T   [DEMB][E]
constexpr size_t O_WG_M  = O_WG_H  + N_WG;
constexpr size_t O_GR_H  = O_WG_M  + N_WG;    // graph_rep^T [DEMB][E]
constexpr size_t O_GR_M  = O_GR_H  + N_GR;
constexpr size_t O_WD1_H = O_GR_M  + N_GR;    // Wd1^T [DIS][SYM]
constexpr size_t O_WD1_M = O_WD1_H + N_WD1;
constexpr size_t O_W1_H  = O_WD1_M + N_WD1;   // W1^T  [HID][DEMB]
constexpr size_t O_W1_M  = O_W1_H  + N_W1;
constexpr size_t O_W2_H  = O_W1_M  + N_W1;    // W2^T  [SYM][HID]
constexpr size_t O_W2_M  = O_W2_H  + N_W2;
constexpr size_t O_WM1_H = O_W2_M  + N_W2;    // Wm1^T [HID][DST]
constexpr size_t O_WM1_M = O_WM1_H + N_WM1;
constexpr size_t O_MD_H  = O_WM1_M + N_WM1;   // m_d^T [SYM][DIS]
constexpr size_t O_MD_M  = O_MD_H  + N_MD;
constexpr size_t BF_TOTAL = O_MD_M + N_MD;

constexpr size_t F_HM    = 0;
constexpr size_t F_SYMTF = F_HM + (size_t)Bdim * HIDD;
constexpr size_t F_MU    = F_SYMTF + (size_t)Bdim * SYM;
constexpr size_t F_DLOG  = F_MU + Bdim;
constexpr size_t F_TOTAL = F_DLOG + (size_t)Bdim * DIS;

__device__ __align__(16) bf16  g_bf[BF_TOTAL];
__device__ __align__(16) float g_f32[F_TOTAL];

// ---------------- PTX helpers (sm_80-era only) ----------------
__device__ __forceinline__ uint32_t smem_u32(const void* p) {
    uint32_t a;
    asm("{ .reg .u64 t; cvta.to.shared.u64 t, %1; cvt.u32.u64 %0, t; }"
        : "=r"(a) : "l"(p));
    return a;
}
__device__ __forceinline__ void cpasync16(uint32_t dst, const void* src) {
    asm volatile("cp.async.cg.shared.global [%0], [%1], 16;" :: "r"(dst), "l"(src));
}
__device__ __forceinline__ void ldmat_x4(uint32_t* r, uint32_t addr) {
    asm volatile("ldmatrix.sync.aligned.m8n8.x4.shared.b16 {%0,%1,%2,%3}, [%4];"
                 : "=r"(r[0]), "=r"(r[1]), "=r"(r[2]), "=r"(r[3]) : "r"(addr));
}
__device__ __forceinline__ void mma16816(float* d, const uint32_t* a,
                                         uint32_t b0, uint32_t b1) {
    asm volatile("mma.sync.aligned.m16n8k16.row.col.f32.bf16.bf16.f32 "
                 "{%0,%1,%2,%3}, {%4,%5,%6,%7}, {%8,%9}, {%0,%1,%2,%3};"
                 : "+f"(d[0]), "+f"(d[1]), "+f"(d[2]), "+f"(d[3])
                 : "r"(a[0]), "r"(a[1]), "r"(a[2]), "r"(a[3]), "r"(b0), "r"(b1));
}

// ---------------- mma.sync GEMM ----------------
// C[M,N] = act(A @ B + bias); A[M][K], B as BT[N][K], bf16 hi/mid split.
// BM = 32*MT, BN = 128. BK=32. 256 thr, 8 warps (2M x 4N), warp tile (16*MT)x32.
#define BTILE_B 10240           // 128 rows * 80 B (64B data + 16B pad)

template <int ACT, int AMODE, int OMODE, int MT, int MINB>
__global__ __launch_bounds__(256, MINB) void mgemm(
    const bf16* __restrict__ Ah, const bf16* __restrict__ Am,
    const float* __restrict__ Af,
    const bf16* __restrict__ BhT, const bf16* __restrict__ BmT,
    const float* __restrict__ bias, float* __restrict__ C,
    bf16* __restrict__ Ch, bf16* __restrict__ Cm,
    int M, int N, int K,
    const float* __restrict__ mu, const float* __restrict__ symtf,
    const int* __restrict__ sflag, const int* __restrict__ smask) {
    constexpr int BM = 32 * MT;
    constexpr int A_T = BM * 80;            // bytes per A half-tile in smem
    constexpr int STAGE = 2 * A_T + 2 * BTILE_B;
    constexpr int NV = (BM * 8 + 255) / 256;// float4 per thread for A_F32
    constexpr int AI = (BM * 4 + 255) / 256;// cp.async iters for A

    extern __shared__ __align__(128) char smem[];
    uint32_t sb = smem_u32(smem);
    int tid = threadIdx.x, wid = tid >> 5, lane = tid & 31;
    int bx = blockIdx.x, by = blockIdx.y;
    int wm = wid & 1, wn = wid >> 1;

    const bf16* pa_h = (AMODE == A_F32) ? nullptr : Ah + (size_t)by * BM * K;
    const bf16* pa_m = (AMODE == A_PRE) ? Am + (size_t)by * BM * K : pa_h;
    const float* paf = (AMODE == A_F32) ? Af + (size_t)by * BM * K : nullptr;
    const bf16* pb_h = BhT + (size_t)bx * 128 * K;
    const bf16* pb_m = BmT + (size_t)bx * 128 * K;
    int nc = K / 32;

    float acc[MT][4][4];
#pragma unroll
    for (int i = 0; i < MT; i++)
#pragma unroll
        for (int j = 0; j < 4; j++)
#pragma unroll
            for (int q = 0; q < 4; q++) acc[i][j][q] = 0.0f;

    // ---- helpers as lambdas ----
    auto copyB = [&](uint32_t base, int k0) {
#pragma unroll
        for (int h = 0; h < 2; h++) {
            int c = tid + h * 256;
            int row = c >> 2, seg = c & 3;
            uint32_t off = (uint32_t)row * 80u + (uint32_t)seg * 16u;
            size_t g = (size_t)row * K + k0 + seg * 8;
            cpasync16(base + 2 * A_T + off, pb_h + g);
            cpasync16(base + 2 * A_T + BTILE_B + off, pb_m + g);
        }
    };
    auto copyA_pre = [&](uint32_t base, int k0) {
#pragma unroll
        for (int h = 0; h < AI; h++) {
            int c = tid + h * 256;
            if (BM * 4 % 256 != 0 && c >= BM * 4) continue;
            int row = c >> 2, seg = c & 3;
            uint32_t off = (uint32_t)row * 80u + (uint32_t)seg * 16u;
            size_t g = (size_t)row * K + k0 + seg * 8;
            cpasync16(base + off, pa_h + g);
            if (AMODE == A_PRE) cpasync16(base + A_T + off, pa_m + g);
        }
    };
    auto stsA_f32 = [&](char* cbase, const float4* v) {
#pragma unroll
        for (int i = 0; i < NV; i++) {
            int idx = tid + i * 256;
            if (BM * 8 % 256 != 0 && idx >= BM * 8) continue;
            int row = idx >> 3, c4 = idx & 7;
            char* d = cbase + row * 80 + c4 * 8;
            bf16 h0 = __float2bfloat16(v[i].x), h1 = __float2bfloat16(v[i].y);
            bf16 h2 = __float2bfloat16(v[i].z), h3 = __float2bfloat16(v[i].w);
            *(__nv_bfloat162*)(d)     = __halves2bfloat162(h0, h1);
            *(__nv_bfloat162*)(d + 4) = __halves2bfloat162(h2, h3);
            char* dm = d + A_T;
            *(__nv_bfloat162*)(dm)     = __halves2bfloat162(
                __float2bfloat16(v[i].x - __bfloat162float(h0)),
                __float2bfloat16(v[i].y - __bfloat162float(h1)));
            *(__nv_bfloat162*)(dm + 4) = __halves2bfloat162(
                __float2bfloat16(v[i].z - __bfloat162float(h2)),
                __float2bfloat16(v[i].w - __bfloat162float(h3)));
        }
    };
    auto ldgA_f32 = [&](float4* v, int k0) {
#pragma unroll
        for (int i = 0; i < NV; i++) {
            int idx = tid + i * 256;
            if (BM * 8 % 256 != 0 && idx >= BM * 8) continue;
            int row = idx >> 3, c4 = idx & 7;
            v[i] = *(const float4*)(paf + (size_t)row * K + k0 + c4 * 4);
        }
    };

    // ---- prologue: stage 0 ----
    if (AMODE == A_F32) {
        float4 v0[NV];
        ldgA_f32(v0, 0);
        stsA_f32(smem, v0);
    } else {
        copyA_pre(sb, 0);
    }
    copyB(sb, 0);
    asm volatile("cp.async.commit_group;" ::: "memory");
    asm volatile("cp.async.wait_group 0;" ::: "memory");
    __syncthreads();

    // ---- main loop ----
    for (int k = 0; k < nc; k++) {
        int st = k & 1;
        uint32_t sbase = sb + st * STAGE;
        char* cbase_n = smem + (st ^ 1) * STAGE;
        uint32_t sbase_n = sb + (st ^ 1) * STAGE;

        float4 afv[NV];
        bool more = (k + 1 < nc);
        if (more) {
            if (AMODE == A_F32) ldgA_f32(afv, (k + 1) * 32);
            else copyA_pre(sbase_n, (k + 1) * 32);
            copyB(sbase_n, (k + 1) * 32);
            asm volatile("cp.async.commit_group;" ::: "memory");
        }

        uint32_t sA_h = sbase;
        uint32_t sA_m = sbase + A_T;
        uint32_t sB_h = sbase + 2 * A_T;
        uint32_t sB_m = sbase + 2 * A_T + BTILE_B;
#pragma unroll
        for (int kk = 0; kk < 2; kk++) {
            uint32_t kb = kk * 32;
            uint32_t afr[MT][4], bfr[2][4];
            auto ldA = [&](uint32_t aB) {
#pragma unroll
                for (int mt = 0; mt < MT; mt++)
                    ldmat_x4(afr[mt],
                             aB + (uint32_t)(wm * (16 * MT) + mt * 16 + (lane & 15)) * 80
                                + kb + (uint32_t)(lane >> 4) * 16);
            };
            auto ldB = [&](uint32_t bB) {
#pragma unroll
                for (int pr = 0; pr < 2; pr++)
                    ldmat_x4(bfr[pr],
                             bB + (uint32_t)(wn * 32 + pr * 16 + (lane & 15)) * 80
                                + kb + (uint32_t)(lane >> 4) * 16);
            };
            auto domma = [&]() {
#pragma unroll
                for (int mt = 0; mt < MT; mt++)
#pragma unroll
                    for (int nt = 0; nt < 4; nt++)
                        mma16816(acc[mt][nt], afr[mt],
                                 bfr[nt >> 1][nt & 1], bfr[nt >> 1][(nt & 1) + 2]);
            };
            // fragment-reuse ordering: ah*bh, ah*bm (A frags reused), am*bh
            ldA(sA_h); ldB(sB_h); domma();
            ldB(sB_m); domma();
            if (AMODE != A_EXACT) {
                ldA(sA_m); ldB(sB_h); domma();
            }
        }

        if (more) {
            if (AMODE == A_F32) stsA_f32(cbase_n, afv);
            asm volatile("cp.async.wait_group 0;" ::: "memory");
        }
        __syncthreads();
    }

    // ---------------- epilogue ----------------
#pragma unroll
    for (int mt = 0; mt < MT; mt++) {
#pragma unroll
        for (int nt = 0; nt < 4; nt++) {
#pragma unroll
            for (int i2 = 0; i2 < 2; i2++) {
                int row = by * BM + wm * (16 * MT) + mt * 16 + (lane >> 2) + i2 * 8;
                int col = bx * 128 + wn * 32 + nt * 8 + (lane & 3) * 2;
                float v0 = acc[mt][nt][i2 * 2 + 0];
                float v1 = acc[mt][nt][i2 * 2 + 1];
                if (bias) { v0 += bias[col]; v1 += bias[col + 1]; }
                if (ACT == ACT_RELU) {
                    v0 = fmaxf(v0, 0.0f); v1 = fmaxf(v1, 0.0f);
                } else if (ACT == ACT_FSIG) {
                    v0 = (v0 > 0.0f) ? 1.0f / (1.0f + expf(-v0)) : v0;
                    v1 = (v1 > 0.0f) ? 1.0f / (1.0f + expf(-v1)) : v1;
                } else if (ACT == ACT_FINAL) {
                    float m = mu[row];
                    size_t o = (size_t)row * SYM + col;
                    float p0 = 1.0f / (1.0f + expf(-v0));
                    float p1 = 1.0f / (1.0f + expf(-v1));
                    v0 = (m * p0 + (1.0f - m) * symtf[o]) *
                         (float)sflag[o] * (float)smask[o];
                    v1 = (m * p1 + (1.0f - m) * symtf[o + 1]) *
                         (float)sflag[o + 1] * (float)smask[o + 1];
                }
                if (OMODE == OUT_F32) {
                    *(float2*)(C + (size_t)row * N + col) = make_float2(v0, v1);
                } else if (OMODE == OUT_SPLIT) {
                    bf16 h0 = __float2bfloat16(v0), h1 = __float2bfloat16(v1);
                    size_t o = (size_t)row * N + col;
                    *(__nv_bfloat162*)(Ch + o) = __halves2bfloat162(h0, h1);
                    *(__nv_bfloat162*)(Cm + o) = __halves2bfloat162(
                        __float2bfloat16(v0 - __bfloat162float(h0)),
                        __float2bfloat16(v1 - __bfloat162float(h1)));
                } else {  // OUT_SPLIT_T: [col][row]
                    bf16 h0 = __float2bfloat16(v0), h1 = __float2bfloat16(v1);
                    Ch[(size_t)col * M + row] = h0;
                    Ch[(size_t)(col + 1) * M + row] = h1;
                    Cm[(size_t)col * M + row] =
                        __float2bfloat16(v0 - __bfloat162float(h0));
                    Cm[(size_t)(col + 1) * M + row] =
                        __float2bfloat16(v1 - __bfloat162float(h1));
                }
            }
        }
    }
}

// ---------------- prep / split kernels ----------------
__global__ void prep_kernel(const int* __restrict__ dialog_state,
                            const int* __restrict__ sym_mask,
                            bf16* __restrict__ state_bf,
                            bf16* __restrict__ symmask_bf) {
    int i = blockIdx.x * blockDim.x + threadIdx.x;
    if (i < Bdim * DST) {
        int v = dialog_state[i];
        state_bf[i] = __float2bfloat16((v == 1) ? 1.0f : ((v == -1) ? -1.0f : 0.0f));
    }
    if (i < Bdim * SYM) symmask_bf[i] = __float2bfloat16((float)sym_mask[i]);
}

// transpose + split one 32x32 tile: in [K][N] fp32 -> hiT/midT [N][K] bf16.
__device__ __forceinline__ void splitT_tile(const float* __restrict__ in,
                                            bf16* __restrict__ hiT,
                                            bf16* __restrict__ midT,
                                            int K, int N, int n0, int k0,
                                            float (*t)[33]) {
    int tx = threadIdx.x, ty = threadIdx.y;
#pragma unroll
    for (int j = ty; j < 32; j += 8)
        t[j][tx] = in[(size_t)(k0 + j) * N + n0 + tx];
    __syncthreads();
#pragma unroll
    for (int j = ty; j < 32; j += 8) {
        float v = t[tx][j];
        bf16 h = __float2bfloat16(v);
        size_t o = (size_t)(n0 + j) * K + k0 + tx;
        hiT[o] = h;
        midT[o] = __float2bfloat16(v - __bfloat162float(h));
    }
}

__global__ void splitT_kernel(const float* __restrict__ in,
                              bf16* __restrict__ hiT, bf16* __restrict__ midT,
                              int K, int N) {
    __shared__ float t[32][33];
    splitT_tile(in, hiT, midT, K, N, blockIdx.x * 32, blockIdx.y * 32, t);
}

// batched split for the 5 remaining weights (one launch)
__global__ void splitT_batch(const float* __restrict__ Wd1,
                             const float* __restrict__ W1,
                             const float* __restrict__ W2,
                             const float* __restrict__ Wm1,
                             const float* __restrict__ m_d,
                             bf16* __restrict__ bp) {
    __shared__ float t[32][33];
    int b = blockIdx.x;
    const float* in; bf16 *hiT, *midT; int K, N, tile;
    if (b < 64)        { in = Wd1; hiT = bp + O_WD1_H; midT = bp + O_WD1_M; K = SYM;  N = DIS;  tile = b; }
    else if (b < 320)  { in = W1;  hiT = bp + O_W1_H;  midT = bp + O_W1_M;  K = DEMB; N = HIDD; tile = b - 64; }
    else if (b < 832)  { in = W2;  hiT = bp + O_W2_H;  midT = bp + O_W2_M;  K = HIDD; N = SYM;  tile = b - 320; }
    else if (b < 1472) { in = Wm1; hiT = bp + O_WM1_H; midT = bp + O_WM1_M; K = DST;  N = HIDD; tile = b - 832; }
    else               { in = m_d; hiT = bp + O_MD_H;  midT = bp + O_MD_M;  K = DIS;  N = SYM;  tile = b - 1472; }
    int ntx = N / 32;
    splitT_tile(in, hiT, midT, K, N, (tile % ntx) * 32, (tile / ntx) * 32, t);
}

__global__ void softmax_mask_kernel(const float* __restrict__ logits,
                                    const int* __restrict__ dmask,
                                    float* __restrict__ out,
                                    bf16* __restrict__ oh, bf16* __restrict__ om) {
    int gw = (blockIdx.x * blockDim.x + threadIdx.x) >> 5;
    int lane = threadIdx.x & 31;
    if (gw >= Bdim) return;
    const float* row = logits + (size_t)gw * DIS;
    float v0 = row[lane], v1 = row[lane + 32], v2 = row[lane + 64], v3 = row[lane + 96];
    float mx = fmaxf(fmaxf(v0, v1), fmaxf(v2, v3));
#pragma unroll
    for (int o = 16; o; o >>= 1) mx = fmaxf(mx, __shfl_xor_sync(0xffffffffu, mx, o));
    v0 = expf(v0 - mx); v1 = expf(v1 - mx); v2 = expf(v2 - mx); v3 = expf(v3 - mx);
    float s = v0 + v1 + v2 + v3;
#pragma unroll
    for (int o = 16; o; o >>= 1) s += __shfl_xor_sync(0xffffffffu, s, o);
    float inv = 1.0f / s;
    const int* dm = dmask + (size_t)gw * DIS;
    size_t base = (size_t)gw * DIS;
#pragma unroll
    for (int q = 0; q < 4; q++) {
        float v = (q == 0 ? v0 : q == 1 ? v1 : q == 2 ? v2 : v3) * inv *
                  (float)dm[lane + q * 32];
        size_t o = base + lane + q * 32;
        out[o] = v;
        bf16 h = __float2bfloat16(v);
        oh[o] = h;
        om[o] = __float2bfloat16(v - __bfloat162float(h));
    }
}

__global__ void mu_kernel(const float* __restrict__ hm,
                          const float* __restrict__ Wm2,
                          const float* __restrict__ bm2,
                          float* __restrict__ mu) {
    int gw = (blockIdx.x * blockDim.x + threadIdx.x) >> 5;
    int lane = threadIdx.x & 31;
    if (gw >= Bdim) return;
    const float* row = hm + (size_t)gw * HIDD;
    float s = 0.0f;
#pragma unroll
    for (int j = 0; j < HIDD / 32; j++)
        s = fmaf(row[lane + 32 * j], Wm2[lane + 32 * j], s);
#pragma unroll
    for (int o = 16; o; o >>= 1) s += __shfl_xor_sync(0xffffffffu, s, o);
    if (lane == 0) mu[gw] = 1.0f / (1.0f + expf(-(s + bm2[0])));
}

// ---------------- launch ----------------
#define SMEM_MT2 (2 * (2 * 64 * 80 + 2 * BTILE_B))    // 61440
#define SMEM_MT1 (2 * (2 * 32 * 80 + 2 * BTILE_B))    // 51200

extern "C" void kernel_launch(void* const* d_in, const int* in_sizes, int n_in,
                              void* d_out, int out_size) {
    const int*   dialog_state  = (const int*)d_in[0];
    const float* dsr           = (const float*)d_in[1];
    const float* kg_adj        = (const float*)d_in[2];
    const int*   sym_flag      = (const int*)d_in[3];
    const int*   sym_mask      = (const int*)d_in[4];
    const int*   disease_mask  = (const int*)d_in[5];
    const int*   symptoms_mask = (const int*)d_in[6];
    const float* W_g  = (const float*)d_in[7];
    const float* Wd1  = (const float*)d_in[8];
    const float* bd1  = (const float*)d_in[9];
    const float* W1   = (const float*)d_in[10];
    const float* b1   = (const float*)d_in[11];
    const float* W2   = (const float*)d_in[12];
    const float* b2   = (const float*)d_in[13];
    const float* Wm1  = (const float*)d_in[14];
    const float* bm1  = (const float*)d_in[15];
    const float* Wm2  = (const float*)d_in[16];
    const float* bm2  = (const float*)d_in[17];
    const float* m_d  = (const float*)d_in[18];

    float* out = (float*)d_out;
    float* disease_out = out;
    float* symptom_out = out + (size_t)Bdim * DIS;

    bf16* bp = nullptr;  float* fp = nullptr;
    cudaGetSymbolAddress((void**)&bp, g_bf);
    cudaGetSymbolAddress((void**)&fp, g_f32);

    float* hm      = fp + F_HM;
    float* symtf   = fp + F_SYMTF;
    float* mu      = fp + F_MU;
    float* dlogits = fp + F_DLOG;

    cudaFuncSetAttribute(mgemm<ACT_RELU, A_F32, OUT_SPLIT_T, 1, 4>, cudaFuncAttributeMaxDynamicSharedMemorySize, SMEM_MT1);
    cudaFuncSetAttribute(mgemm<ACT_NONE, A_F32, OUT_SPLIT, 1, 4>,   cudaFuncAttributeMaxDynamicSharedMemorySize, SMEM_MT1);
    cudaFuncSetAttribute(mgemm<ACT_NONE, A_EXACT, OUT_F32, 1, 4>,   cudaFuncAttributeMaxDynamicSharedMemorySize, SMEM_MT1);
    cudaFuncSetAttribute(mgemm<ACT_FSIG, A_PRE, OUT_F32, 2, 3>,     cudaFuncAttributeMaxDynamicSharedMemorySize, SMEM_MT2);
    cudaFuncSetAttribute(mgemm<ACT_RELU, A_PRE, OUT_SPLIT, 2, 3>,   cudaFuncAttributeMaxDynamicSharedMemorySize, SMEM_MT2);
    cudaFuncSetAttribute(mgemm<ACT_RELU, A_EXACT, OUT_F32, 2, 3>,   cudaFuncAttributeMaxDynamicSharedMemorySize, SMEM_MT2);
    cudaFuncSetAttribute(mgemm<ACT_FINAL, A_PRE, OUT_F32, 2, 3>,    cudaFuncAttributeMaxDynamicSharedMemorySize, SMEM_MT2);

    // Launch order: my #4 = overall 6th launch, so ncu -s 5 -c 1 profiles G2.
    // 1: prep
    prep_kernel<<<(Bdim * DST + 255) / 256, 256>>>(dialog_state, sym_mask,
                                                   bp + O_STU, bp + O_SYMM);
    // 2: split W_g
    dim3 tb(32, 8);
    splitT_kernel<<<dim3(DEMB / 32, Edim / 32), tb>>>(W_g, bp + O_WG_H, bp + O_WG_M, Edim, DEMB);

    // 3: G1: graph_rep^T = relu(kg_adj @ W_g)^T -> split T; MT=1 (256 CTAs)
    mgemm<ACT_RELU, A_F32, OUT_SPLIT_T, 1, 4><<<dim3(DEMB / 128, Edim / 32), 256, SMEM_MT1>>>(
        nullptr, nullptr, kg_adj, bp + O_WG_H, bp + O_WG_M,
        nullptr, nullptr, bp + O_GR_H, bp + O_GR_M,
        Edim, DEMB, Edim, nullptr, nullptr, nullptr, nullptr);

    // 4: G2: state = dsr @ graph_rep -> split; MT=1 (512 CTAs, 4/SM)
    mgemm<ACT_NONE, A_F32, OUT_SPLIT, 1, 4><<<dim3(DEMB / 128, Bdim / 32), 256, SMEM_MT1>>>(
        nullptr, nullptr, dsr, bp + O_GR_H, bp + O_GR_M,
        nullptr, nullptr, bp + O_ST_H, bp + O_ST_M,
        Bdim, DEMB, Edim, nullptr, nullptr, nullptr, nullptr);

    // 5: split remaining weights (batched, one launch)
    splitT_batch<<<1536, tb>>>(Wd1, W1, W2, Wm1, m_d, bp);

    // 6: G3: dlogits = sym_mask @ Wd1 + bd1 (A exact); MT=1 (256 CTAs)
    mgemm<ACT_NONE, A_EXACT, OUT_F32, 1, 4><<<dim3(DIS / 128, Bdim / 32), 256, SMEM_MT1>>>(
        bp + O_SYMM, nullptr, nullptr, bp + O_WD1_H, bp + O_WD1_M,
        bd1, dlogits, nullptr, nullptr,
        Bdim, DIS, SYM, nullptr, nullptr, nullptr, nullptr);

    // 7: softmax
    softmax_mask_kernel<<<Bdim / 8, 256>>>(dlogits, disease_mask, disease_out,
                                           bp + O_DIS_H, bp + O_DIS_M);

    // 8: G4: symtf = filter_sig(disease @ m_d); MT=2 (512 CTAs)
    mgemm<ACT_FSIG, A_PRE, OUT_F32, 2, 3><<<dim3(SYM / 128, Bdim / 64), 256, SMEM_MT2>>>(
        bp + O_DIS_H, bp + O_DIS_M, nullptr, bp + O_MD_H, bp + O_MD_M,
        nullptr, symtf, nullptr, nullptr,
        Bdim, SYM, DIS, nullptr, nullptr, nullptr, nullptr);

    // 9: G5: h1 = relu(state @ W1 + b1) -> split; MT=2 (1024 CTAs)
    mgemm<ACT_RELU, A_PRE, OUT_SPLIT, 2, 3><<<dim3(HIDD / 128, Bdim / 64), 256, SMEM_MT2>>>(
        bp + O_ST_H, bp + O_ST_M, nullptr, bp + O_W1_H, bp + O_W1_M,
        b1, nullptr, bp + O_H1_H, bp + O_H1_M,
        Bdim, HIDD, DEMB, nullptr, nullptr, nullptr, nullptr);

    // 10: G6: hm = relu(state_ @ Wm1 + bm1) (A exact); MT=2 (1024 CTAs)
    mgemm<ACT_RELU, A_EXACT, OUT_F32, 2, 3><<<dim3(HIDD / 128, Bdim / 64), 256, SMEM_MT2>>>(
        bp + O_STU, nullptr, nullptr, bp + O_WM1_H, bp + O_WM1_M,
        bm1, hm, nullptr, nullptr,
        Bdim, HIDD, DST, nullptr, nullptr, nullptr, nullptr);

    // 11: mu
    mu_kernel<<<Bdim / 8, 256>>>(hm, Wm2, bm2, mu);

    // 12: G7: symptom_final; MT=2 (512 CTAs)
    mgemm<ACT_FINAL, A_PRE, OUT_F32, 2, 3><<<dim3(SYM / 128, Bdim / 64), 256, SMEM_MT2>>>(
        bp + O_H1_H, bp + O_H1_M, nullptr, bp + O_W2_H, bp + O_W2_M,
        b2, symptom_out, nullptr, nullptr,
        Bdim, SYM, HIDD, mu, symtf, sym_flag, symptoms_mask);
}

// round 14
// speedup vs baseline: 1.1019x; 1.1019x over previous
#include <cuda_runtime.h>
#include <cuda_bf16.h>
#include <math.h>
#include <stdint.h>

#define Bdim 8192
#define Edim 4096
#define DEMB 256
#define HIDD 1024
#define DIS 128
#define SYM 512
#define DST 640   // DIS + SYM

enum { ACT_NONE = 0, ACT_RELU = 1, ACT_FSIG = 2, ACT_FINAL = 3 };
enum { OUT_F32 = 0, OUT_SPLIT = 1, OUT_SPLIT_T = 2 };
enum { A_PRE = 0, A_EXACT = 1, A_F32 = 2 };

typedef __nv_bfloat16 bf16;

// ---------------- scratch layout ----------------
constexpr size_t N_ST   = (size_t)Bdim * DEMB;
constexpr size_t N_H1   = (size_t)Bdim * HIDD;
constexpr size_t N_DIS  = (size_t)Bdim * DIS;
constexpr size_t N_SYMM = (size_t)Bdim * SYM;
constexpr size_t N_STU  = (size_t)Bdim * DST;
constexpr size_t N_WG   = (size_t)Edim * DEMB;
constexpr size_t N_GR   = (size_t)Edim * DEMB;
constexpr size_t N_WD1  = (size_t)SYM * DIS;
constexpr size_t N_W1   = (size_t)DEMB * HIDD;
constexpr size_t N_W2   = (size_t)HIDD * SYM;
constexpr size_t N_WM1  = (size_t)DST * HIDD;
constexpr size_t N_MD   = (size_t)DIS * SYM;

constexpr size_t O_ST_H  = 0;
constexpr size_t O_ST_M  = O_ST_H  + N_ST;
constexpr size_t O_H1_H  = O_ST_M  + N_ST;
constexpr size_t O_H1_M  = O_H1_H  + N_H1;
constexpr size_t O_DIS_H = O_H1_M  + N_H1;
constexpr size_t O_DIS_M = O_DIS_H + N_DIS;
constexpr size_t O_SYMM  = O_DIS_M + N_DIS;
constexpr size_t O_STU   = O_SYMM  + N_SYMM;
constexpr size_t O_WG_H  = O_STU   + N_STU;   // W_g^T   [DEMB][E]
constexpr size_t O_WG_M  = O_WG_H  + N_WG;
constexpr size_t O_GR_H  = O_WG_M  + N_WG;    // graph_rep^T [DEMB][E]
constexpr size_t O_GR_M  = O_GR_H  + N_GR;
constexpr size_t O_WD1_H = O_GR_M  + N_GR;    // Wd1^T [DIS][SYM]
constexpr size_t O_WD1_M = O_WD1_H + N_WD1;
constexpr size_t O_W1_H  = O_WD1_M + N_WD1;   // W1^T  [HID][DEMB]
constexpr size_t O_W1_M  = O_W1_H  + N_W1;
constexpr size_t O_W2_H  = O_W1_M  + N_W1;    // W2^T  [SYM][HID]
constexpr size_t O_W2_M  = O_W2_H  + N_W2;
constexpr size_t O_WM1_H = O_W2_M  + N_W2;    // Wm1^T [HID][DST]
constexpr size_t O_WM1_M = O_WM1_H + N_WM1;
constexpr size_t O_MD_H  = O_WM1_M + N_WM1;   // m_d^T [SYM][DIS]
constexpr size_t O_MD_M  = O_MD_H  + N_MD;
constexpr size_t BF_TOTAL = O_MD_M + N_MD;

constexpr size_t F_HM    = 0;
constexpr size_t F_SYMTF = F_HM + (size_t)Bdim * HIDD;
constexpr size_t F_MU    = F_SYMTF + (size_t)Bdim * SYM;
constexpr size_t F_DLOG  = F_MU + Bdim;
constexpr size_t F_TOTAL = F_DLOG + (size_t)Bdim * DIS;

__device__ __align__(16) bf16  g_bf[BF_TOTAL];
__device__ __align__(16) float g_f32[F_TOTAL];

// ---------------- PTX helpers (sm_80-era only) ----------------
__device__ __forceinline__ uint32_t smem_u32(const void* p) {
    uint32_t a;
    asm("{ .reg .u64 t; cvta.to.shared.u64 t, %1; cvt.u32.u64 %0, t; }"
        : "=r"(a) : "l"(p));
    return a;
}
__device__ __forceinline__ void cpasync16(uint32_t dst, const void* src) {
    asm volatile("cp.async.cg.shared.global [%0], [%1], 16;" :: "r"(dst), "l"(src));
}
__device__ __forceinline__ void ldmat_x4(uint32_t* r, uint32_t addr) {
    asm volatile("ldmatrix.sync.aligned.m8n8.x4.shared.b16 {%0,%1,%2,%3}, [%4];"
                 : "=r"(r[0]), "=r"(r[1]), "=r"(r[2]), "=r"(r[3]) : "r"(addr));
}
__device__ __forceinline__ void mma16816(float* d, const uint32_t* a,
                                         uint32_t b0, uint32_t b1) {
    asm volatile("mma.sync.aligned.m16n8k16.row.col.f32.bf16.bf16.f32 "
                 "{%0,%1,%2,%3}, {%4,%5,%6,%7}, {%8,%9}, {%0,%1,%2,%3};"
                 : "+f"(d[0]), "+f"(d[1]), "+f"(d[2]), "+f"(d[3])
                 : "r"(a[0]), "r"(a[1]), "r"(a[2]), "r"(a[3]), "r"(b0), "r"(b1));
}

// ---------------- mma.sync GEMM (3-stage cp.async pipeline) ----------------
// C[M,N] = act(A @ B + bias); A[M][K], B as BT[N][K], bf16 hi/mid split.
// BM = 32*MT, BN = 128. BK=32. 256 thr, 8 warps (2M x 4N), warp tile (16*MT)x32.
#define BTILE_B 10240           // 128 rows * 80 B (64B data + 16B pad)

template <int ACT, int AMODE, int OMODE, int MT, int MINB>
__global__ __launch_bounds__(256, MINB) void mgemm(
    const bf16* __restrict__ Ah, const bf16* __restrict__ Am,
    const float* __restrict__ Af,
    const bf16* __restrict__ BhT, const bf16* __restrict__ BmT,
    const float* __restrict__ bias, float* __restrict__ C,
    bf16* __restrict__ Ch, bf16* __restrict__ Cm,
    int M, int N, int K,
    const float* __restrict__ mu, const float* __restrict__ symtf,
    const int* __restrict__ sflag, const int* __restrict__ smask) {
    constexpr int BM = 32 * MT;
    constexpr int A_T = BM * 80;            // bytes per A half-tile in smem
    constexpr int STAGE = 2 * A_T + 2 * BTILE_B;
    constexpr int NV = (BM * 8 + 255) / 256;// float4 per thread for A_F32
    constexpr int AI = (BM * 4 + 255) / 256;// cp.async iters for A

    extern __shared__ __align__(128) char smem[];
    uint32_t sb = smem_u32(smem);
    int tid = threadIdx.x, wid = tid >> 5, lane = tid & 31;
    int bx = blockIdx.x, by = blockIdx.y;
    int wm = wid & 1, wn = wid >> 1;

    const bf16* pa_h = (AMODE == A_F32) ? nullptr : Ah + (size_t)by * BM * K;
    const bf16* pa_m = (AMODE == A_PRE) ? Am + (size_t)by * BM * K : pa_h;
    const float* paf = (AMODE == A_F32) ? Af + (size_t)by * BM * K : nullptr;
    const bf16* pb_h = BhT + (size_t)bx * 128 * K;
    const bf16* pb_m = BmT + (size_t)bx * 128 * K;
    int nc = K / 32;   // >= 4 for all our GEMMs

    float acc[MT][4][4];
#pragma unroll
    for (int i = 0; i < MT; i++)
#pragma unroll
        for (int j = 0; j < 4; j++)
#pragma unroll
            for (int q = 0; q < 4; q++) acc[i][j][q] = 0.0f;

    // ---- helpers ----
    auto copyB = [&](uint32_t base, int k0) {
#pragma unroll
        for (int h = 0; h < 2; h++) {
            int c = tid + h * 256;
            int row = c >> 2, seg = c & 3;
            uint32_t off = (uint32_t)row * 80u + (uint32_t)seg * 16u;
            size_t g = (size_t)row * K + k0 + seg * 8;
            cpasync16(base + 2 * A_T + off, pb_h + g);
            cpasync16(base + 2 * A_T + BTILE_B + off, pb_m + g);
        }
    };
    auto copyA_pre = [&](uint32_t base, int k0) {
#pragma unroll
        for (int h = 0; h < AI; h++) {
            int c = tid + h * 256;
            if (BM * 4 % 256 != 0 && c >= BM * 4) continue;
            int row = c >> 2, seg = c & 3;
            uint32_t off = (uint32_t)row * 80u + (uint32_t)seg * 16u;
            size_t g = (size_t)row * K + k0 + seg * 8;
            cpasync16(base + off, pa_h + g);
            if (AMODE == A_PRE) cpasync16(base + A_T + off, pa_m + g);
        }
    };
    auto stsA_f32 = [&](char* cbase, const float4* v) {
#pragma unroll
        for (int i = 0; i < NV; i++) {
            int idx = tid + i * 256;
            if (BM * 8 % 256 != 0 && idx >= BM * 8) continue;
            int row = idx >> 3, c4 = idx & 7;
            char* d = cbase + row * 80 + c4 * 8;
            bf16 h0 = __float2bfloat16(v[i].x), h1 = __float2bfloat16(v[i].y);
            bf16 h2 = __float2bfloat16(v[i].z), h3 = __float2bfloat16(v[i].w);
            *(__nv_bfloat162*)(d)     = __halves2bfloat162(h0, h1);
            *(__nv_bfloat162*)(d + 4) = __halves2bfloat162(h2, h3);
            char* dm = d + A_T;
            *(__nv_bfloat162*)(dm)     = __halves2bfloat162(
                __float2bfloat16(v[i].x - __bfloat162float(h0)),
                __float2bfloat16(v[i].y - __bfloat162float(h1)));
            *(__nv_bfloat162*)(dm + 4) = __halves2bfloat162(
                __float2bfloat16(v[i].z - __bfloat162float(h2)),
                __float2bfloat16(v[i].w - __bfloat162float(h3)));
        }
    };
    auto ldgA_f32 = [&](float4* v, int k0) {
#pragma unroll
        for (int i = 0; i < NV; i++) {
            int idx = tid + i * 256;
            if (BM * 8 % 256 != 0 && idx >= BM * 8) continue;
            int row = idx >> 3, c4 = idx & 7;
            v[i] = *(const float4*)(paf + (size_t)row * K + k0 + c4 * 4);
        }
    };

    // ---- prologue: preload chunks 0 and 1 (one commit group each) ----
    if (AMODE == A_F32) {
        float4 v0[NV];
        ldgA_f32(v0, 0);  stsA_f32(smem, v0);
    } else {
        copyA_pre(sb, 0);
    }
    copyB(sb, 0);
    asm volatile("cp.async.commit_group;" ::: "memory");
    if (AMODE == A_F32) {
        float4 v1[NV];
        ldgA_f32(v1, 32); stsA_f32(smem + STAGE, v1);
    } else {
        copyA_pre(sb + STAGE, 32);
    }
    copyB(sb + STAGE, 32);
    asm volatile("cp.async.commit_group;" ::: "memory");

    // ---- main loop: 3-stage; chunk k+2 always in flight during MMA(k) ----
    int scur = 0;
    for (int k = 0; k < nc; k++) {
        if (k + 1 < nc) asm volatile("cp.async.wait_group 1;" ::: "memory");
        else            asm volatile("cp.async.wait_group 0;" ::: "memory");
        __syncthreads();   // chunk k landed; all warps done with MMA(k-1)

        bool pre = (k + 2 < nc);
        int spre = scur + 2; if (spre >= 3) spre -= 3;
        float4 afv[NV];
        if (pre && AMODE == A_F32) ldgA_f32(afv, (k + 2) * 32);

        uint32_t sbase = sb + scur * STAGE;
        uint32_t sA_h = sbase;
        uint32_t sA_m = sbase + A_T;
        uint32_t sB_h = sbase + 2 * A_T;
        uint32_t sB_m = sbase + 2 * A_T + BTILE_B;
#pragma unroll
        for (int kk = 0; kk < 2; kk++) {
            uint32_t kb = kk * 32;
            uint32_t afr[MT][4], bfr[2][4];
            auto ldA = [&](uint32_t aB) {
#pragma unroll
                for (int mt = 0; mt < MT; mt++)
                    ldmat_x4(afr[mt],
                             aB + (uint32_t)(wm * (16 * MT) + mt * 16 + (lane & 15)) * 80
                                + kb + (uint32_t)(lane >> 4) * 16);
            };
            auto ldB = [&](uint32_t bB) {
#pragma unroll
                for (int pr = 0; pr < 2; pr++)
                    ldmat_x4(bfr[pr],
                             bB + (uint32_t)(wn * 32 + pr * 16 + (lane & 15)) * 80
                                + kb + (uint32_t)(lane >> 4) * 16);
            };
            auto domma = [&]() {
#pragma unroll
                for (int mt = 0; mt < MT; mt++)
#pragma unroll
                    for (int nt = 0; nt < 4; nt++)
                        mma16816(acc[mt][nt], afr[mt],
                                 bfr[nt >> 1][nt & 1], bfr[nt >> 1][(nt & 1) + 2]);
            };
            // fragment-reuse ordering: ah*bh, ah*bm (A frags reused), am*bh
            ldA(sA_h); ldB(sB_h); domma();
            ldB(sB_m); domma();
            if (AMODE != A_EXACT) {
                ldA(sA_m); ldB(sB_h); domma();
            }
        }

        if (pre) {
            uint32_t sbase_n = sb + spre * STAGE;
            char* cbase_n = smem + spre * STAGE;
            if (AMODE == A_F32) stsA_f32(cbase_n, afv);
            else copyA_pre(sbase_n, (k + 2) * 32);
            copyB(sbase_n, (k + 2) * 32);
            asm volatile("cp.async.commit_group;" ::: "memory");
        }
        scur = (scur + 1 == 3) ? 0 : scur + 1;
    }

    // ---------------- epilogue ----------------
#pragma unroll
    for (int mt = 0; mt < MT; mt++) {
#pragma unroll
        for (int nt = 0; nt < 4; nt++) {
#pragma unroll
            for (int i2 = 0; i2 < 2; i2++) {
                int row = by * BM + wm * (16 * MT) + mt * 16 + (lane >> 2) + i2 * 8;
                int col = bx * 128 + wn * 32 + nt * 8 + (lane & 3) * 2;
                float v0 = acc[mt][nt][i2 * 2 + 0];
                float v1 = acc[mt][nt][i2 * 2 + 1];
                if (bias) { v0 += bias[col]; v1 += bias[col + 1]; }
                if (ACT == ACT_RELU) {
                    v0 = fmaxf(v0, 0.0f); v1 = fmaxf(v1, 0.0f);
                } else if (ACT == ACT_FSIG) {
                    v0 = (v0 > 0.0f) ? 1.0f / (1.0f + expf(-v0)) : v0;
                    v1 = (v1 > 0.0f) ? 1.0f / (1.0f + expf(-v1)) : v1;
                } else if (ACT == ACT_FINAL) {
                    float m = mu[row];
                    size_t o = (size_t)row * SYM + col;
                    float p0 = 1.0f / (1.0f + expf(-v0));
                    float p1 = 1.0f / (1.0f + expf(-v1));
                    v0 = (m * p0 + (1.0f - m) * symtf[o]) *
                         (float)sflag[o] * (float)smask[o];
                    v1 = (m * p1 + (1.0f - m) * symtf[o + 1]) *
                         (float)sflag[o + 1] * (float)smask[o + 1];
                }
                if (OMODE == OUT_F32) {
                    *(float2*)(C + (size_t)row * N + col) = make_float2(v0, v1);
                } else if (OMODE == OUT_SPLIT) {
                    bf16 h0 = __float2bfloat16(v0), h1 = __float2bfloat16(v1);
                    size_t o = (size_t)row * N + col;
                    *(__nv_bfloat162*)(Ch + o) = __halves2bfloat162(h0, h1);
                    *(__nv_bfloat162*)(Cm + o) = __halves2bfloat162(
                        __float2bfloat16(v0 - __bfloat162float(h0)),
                        __float2bfloat16(v1 - __bfloat162float(h1)));
                } else {  // OUT_SPLIT_T: [col][row]
                    bf16 h0 = __float2bfloat16(v0), h1 = __float2bfloat16(v1);
                    Ch[(size_t)col * M + row] = h0;
                    Ch[(size_t)(col + 1) * M + row] = h1;
                    Cm[(size_t)col * M + row] =
                        __float2bfloat16(v0 - __bfloat162float(h0));
                    Cm[(size_t)(col + 1) * M + row] =
                        __float2bfloat16(v1 - __bfloat162float(h1));
                }
            }
        }
    }
}

// ---------------- prep / split kernels ----------------
__global__ void prep_kernel(const int* __restrict__ dialog_state,
                            const int* __restrict__ sym_mask,
                            bf16* __restrict__ state_bf,
                            bf16* __restrict__ symmask_bf) {
    int i = blockIdx.x * blockDim.x + threadIdx.x;
    if (i < Bdim * DST) {
        int v = dialog_state[i];
        state_bf[i] = __float2bfloat16((v == 1) ? 1.0f : ((v == -1) ? -1.0f : 0.0f));
    }
    if (i < Bdim * SYM) symmask_bf[i] = __float2bfloat16((float)sym_mask[i]);
}

// transpose + split one 32x32 tile: in [K][N] fp32 -> hiT/midT [N][K] bf16.
__device__ __forceinline__ void splitT_tile(const float* __restrict__ in,
                                            bf16* __restrict__ hiT,
                                            bf16* __restrict__ midT,
                                            int K, int N, int n0, int k0,
                                            float (*t)[33]) {
    int tx = threadIdx.x, ty = threadIdx.y;
#pragma unroll
    for (int j = ty; j < 32; j += 8)
        t[j][tx] = in[(size_t)(k0 + j) * N + n0 + tx];
    __syncthreads();
#pragma unroll
    for (int j = ty; j < 32; j += 8) {
        float v = t[tx][j];
        bf16 h = __float2bfloat16(v);
        size_t o = (size_t)(n0 + j) * K + k0 + tx;
        hiT[o] = h;
        midT[o] = __float2bfloat16(v - __bfloat162float(h));
    }
}

__global__ void splitT_kernel(const float* __restrict__ in,
                              bf16* __restrict__ hiT, bf16* __restrict__ midT,
                              int K, int N) {
    __shared__ float t[32][33];
    splitT_tile(in, hiT, midT, K, N, blockIdx.x * 32, blockIdx.y * 32, t);
}

// batched split for the 5 remaining weights (one launch)
__global__ void splitT_batch(const float* __restrict__ Wd1,
                             const float* __restrict__ W1,
                             const float* __restrict__ W2,
                             const float* __restrict__ Wm1,
                             const float* __restrict__ m_d,
                             bf16* __restrict__ bp) {
    __shared__ float t[32][33];
    int b = blockIdx.x;
    const float* in; bf16 *hiT, *midT; int K, N, tile;
    if (b < 64)        { in = Wd1; hiT = bp + O_WD1_H; midT = bp + O_WD1_M; K = SYM;  N = DIS;  tile = b; }
    else if (b < 320)  { in = W1;  hiT = bp + O_W1_H;  midT = bp + O_W1_M;  K = DEMB; N = HIDD; tile = b - 64; }
    else if (b < 832)  { in = W2;  hiT = bp + O_W2_H;  midT = bp + O_W2_M;  K = HIDD; N = SYM;  tile = b - 320; }
    else if (b < 1472) { in = Wm1; hiT = bp + O_WM1_H; midT = bp + O_WM1_M; K = DST;  N = HIDD; tile = b - 832; }
    else               { in = m_d; hiT = bp + O_MD_H;  midT = bp + O_MD_M;  K = DIS;  N = SYM;  tile = b - 1472; }
    int ntx = N / 32;
    splitT_tile(in, hiT, midT, K, N, (tile % ntx) * 32, (tile / ntx) * 32, t);
}

__global__ void softmax_mask_kernel(const float* __restrict__ logits,
                                    const int* __restrict__ dmask,
                                    float* __restrict__ out,
                                    bf16* __restrict__ oh, bf16* __restrict__ om) {
    int gw = (blockIdx.x * blockDim.x + threadIdx.x) >> 5;
    int lane = threadIdx.x & 31;
    if (gw >= Bdim) return;
    const float* row = logits + (size_t)gw * DIS;
    float v0 = row[lane], v1 = row[lane + 32], v2 = row[lane + 64], v3 = row[lane + 96];
    float mx = fmaxf(fmaxf(v0, v1), fmaxf(v2, v3));
#pragma unroll
    for (int o = 16; o; o >>= 1) mx = fmaxf(mx, __shfl_xor_sync(0xffffffffu, mx, o));
    v0 = expf(v0 - mx); v1 = expf(v1 - mx); v2 = expf(v2 - mx); v3 = expf(v3 - mx);
    float s = v0 + v1 + v2 + v3;
#pragma unroll
    for (int o = 16; o; o >>= 1) s += __shfl_xor_sync(0xffffffffu, s, o);
    float inv = 1.0f / s;
    const int* dm = dmask + (size_t)gw * DIS;
    size_t base = (size_t)gw * DIS;
#pragma unroll
    for (int q = 0; q < 4; q++) {
        float v = (q == 0 ? v0 : q == 1 ? v1 : q == 2 ? v2 : v3) * inv *
                  (float)dm[lane + q * 32];
        size_t o = base + lane + q * 32;
        out[o] = v;
        bf16 h = __float2bfloat16(v);
        oh[o] = h;
        om[o] = __float2bfloat16(v - __bfloat162float(h));
    }
}

__global__ void mu_kernel(const float* __restrict__ hm,
                          const float* __restrict__ Wm2,
                          const float* __restrict__ bm2,
                          float* __restrict__ mu) {
    int gw = (blockIdx.x * blockDim.x + threadIdx.x) >> 5;
    int lane = threadIdx.x & 31;
    if (gw >= Bdim) return;
    const float* row = hm + (size_t)gw * HIDD;
    float s = 0.0f;
#pragma unroll
    for (int j = 0; j < HIDD / 32; j++)
        s = fmaf(row[lane + 32 * j], Wm2[lane + 32 * j], s);
#pragma unroll
    for (int o = 16; o; o >>= 1) s += __shfl_xor_sync(0xffffffffu, s, o);
    if (lane == 0) mu[gw] = 1.0f / (1.0f + expf(-(s + bm2[0])));
}

// ---------------- launch ----------------
#define S3_MT2 (3 * (2 * 64 * 80 + 2 * BTILE_B))   // 92160
#define S3_MT1 (3 * (2 * 32 * 80 + 2 * BTILE_B))   // 76800

extern "C" void kernel_launch(void* const* d_in, const int* in_sizes, int n_in,
                              void* d_out, int out_size) {
    const int*   dialog_state  = (const int*)d_in[0];
    const float* dsr           = (const float*)d_in[1];
    const float* kg_adj        = (const float*)d_in[2];
    const int*   sym_flag      = (const int*)d_in[3];
    const int*   sym_mask      = (const int*)d_in[4];
    const int*   disease_mask  = (const int*)d_in[5];
    const int*   symptoms_mask = (const int*)d_in[6];
    const float* W_g  = (const float*)d_in[7];
    const float* Wd1  = (const float*)d_in[8];
    const float* bd1  = (const float*)d_in[9];
    const float* W1   = (const float*)d_in[10];
    const float* b1   = (const float*)d_in[11];
    const float* W2   = (const float*)d_in[12];
    const float* b2   = (const float*)d_in[13];
    const float* Wm1  = (const float*)d_in[14];
    const float* bm1  = (const float*)d_in[15];
    const float* Wm2  = (const float*)d_in[16];
    const float* bm2  = (const float*)d_in[17];
    const float* m_d  = (const float*)d_in[18];

    float* out = (float*)d_out;
    float* disease_out = out;
    float* symptom_out = out + (size_t)Bdim * DIS;

    bf16* bp = nullptr;  float* fp = nullptr;
    cudaGetSymbolAddress((void**)&bp, g_bf);
    cudaGetSymbolAddress((void**)&fp, g_f32);

    float* hm      = fp + F_HM;
    float* symtf   = fp + F_SYMTF;
    float* mu      = fp + F_MU;
    float* dlogits = fp + F_DLOG;

    cudaFuncSetAttribute(mgemm<ACT_RELU, A_F32, OUT_SPLIT_T, 1, 2>, cudaFuncAttributeMaxDynamicSharedMemorySize, S3_MT1);
    cudaFuncSetAttribute(mgemm<ACT_NONE, A_F32, OUT_SPLIT, 2, 2>,   cudaFuncAttributeMaxDynamicSharedMemorySize, S3_MT2);
    cudaFuncSetAttribute(mgemm<ACT_NONE, A_EXACT, OUT_F32, 1, 2>,   cudaFuncAttributeMaxDynamicSharedMemorySize, S3_MT1);
    cudaFuncSetAttribute(mgemm<ACT_FSIG, A_PRE, OUT_F32, 2, 2>,     cudaFuncAttributeMaxDynamicSharedMemorySize, S3_MT2);
    cudaFuncSetAttribute(mgemm<ACT_RELU, A_PRE, OUT_SPLIT, 2, 2>,   cudaFuncAttributeMaxDynamicSharedMemorySize, S3_MT2);
    cudaFuncSetAttribute(mgemm<ACT_RELU, A_EXACT, OUT_F32, 2, 2>,   cudaFuncAttributeMaxDynamicSharedMemorySize, S3_MT2);
    cudaFuncSetAttribute(mgemm<ACT_FINAL, A_PRE, OUT_F32, 2, 2>,    cudaFuncAttributeMaxDynamicSharedMemorySize, S3_MT2);

    // Launch order: my #4 = overall 6th launch, so ncu -s 5 -c 1 profiles G2.
    // 1: prep
    prep_kernel<<<(Bdim * DST + 255) / 256, 256>>>(dialog_state, sym_mask,
                                                   bp + O_STU, bp + O_SYMM);
    // 2: split W_g
    dim3 tb(32, 8);
    splitT_kernel<<<dim3(DEMB / 32, Edim / 32), tb>>>(W_g, bp + O_WG_H, bp + O_WG_M, Edim, DEMB);

    // 3: G1: graph_rep^T = relu(kg_adj @ W_g)^T -> split T; MT=1 (256 CTAs)
    mgemm<ACT_RELU, A_F32, OUT_SPLIT_T, 1, 2><<<dim3(DEMB / 128, Edim / 32), 256, S3_MT1>>>(
        nullptr, nullptr, kg_adj, bp + O_WG_H, bp + O_WG_M,
        nullptr, nullptr, bp + O_GR_H, bp + O_GR_M,
        Edim, DEMB, Edim, nullptr, nullptr, nullptr, nullptr);

    // 4: G2: state = dsr @ graph_rep -> split; MT=2, 3-stage (256 CTAs)
    mgemm<ACT_NONE, A_F32, OUT_SPLIT, 2, 2><<<dim3(DEMB / 128, Bdim / 64), 256, S3_MT2>>>(
        nullptr, nullptr, dsr, bp + O_GR_H, bp + O_GR_M,
        nullptr, nullptr, bp + O_ST_H, bp + O_ST_M,
        Bdim, DEMB, Edim, nullptr, nullptr, nullptr, nullptr);

    // 5: split remaining weights (batched, one launch)
    splitT_batch<<<1536, tb>>>(Wd1, W1, W2, Wm1, m_d, bp);

    // 6: G3: dlogits = sym_mask @ Wd1 + bd1 (A exact); MT=1 (256 CTAs)
    mgemm<ACT_NONE, A_EXACT, OUT_F32, 1, 2><<<dim3(DIS / 128, Bdim / 32), 256, S3_MT1>>>(
        bp + O_SYMM, nullptr, nullptr, bp + O_WD1_H, bp + O_WD1_M,
        bd1, dlogits, nullptr, nullptr,
        Bdim, DIS, SYM, nullptr, nullptr, nullptr, nullptr);

    // 7: softmax
    softmax_mask_kernel<<<Bdim / 8, 256>>>(dlogits, disease_mask, disease_out,
                                           bp + O_DIS_H, bp + O_DIS_M);

    // 8: G4: symtf = filter_sig(disease @ m_d); MT=2 (512 CTAs)
    mgemm<ACT_FSIG, A_PRE, OUT_F32, 2, 2><<<dim3(SYM / 128, Bdim / 64), 256, S3_MT2>>>(
        bp + O_DIS_H, bp + O_DIS_M, nullptr, bp + O_MD_H, bp + O_MD_M,
        nullptr, symtf, nullptr, nullptr,
        Bdim, SYM, DIS, nullptr, nullptr, nullptr, nullptr);

    // 9: G5: h1 = relu(state @ W1 + b1) -> split; MT=2 (1024 CTAs)
    mgemm<ACT_RELU, A_PRE, OUT_SPLIT, 2, 2><<<dim3(HIDD / 128, Bdim / 64), 256, S3_MT2>>>(
        bp + O_ST_H, bp + O_ST_M, nullptr, bp + O_W1_H, bp + O_W1_M,
        b1, nullptr, bp + O_H1_H, bp + O_H1_M,
        Bdim, HIDD, DEMB, nullptr, nullptr, nullptr, nullptr);

    // 10: G6: hm = relu(state_ @ Wm1 + bm1) (A exact); MT=2 (1024 CTAs)
    mgemm<ACT_RELU, A_EXACT, OUT_F32, 2, 2><<<dim3(HIDD / 128, Bdim / 64), 256, S3_MT2>>>(
        bp + O_STU, nullptr, nullptr, bp + O_WM1_H, bp + O_WM1_M,
        bm1, hm, nullptr, nullptr,
        Bdim, HIDD, DST, nullptr, nullptr, nullptr, nullptr);

    // 11: mu
    mu_kernel<<<Bdim / 8, 256>>>(hm, Wm2, bm2, mu);

    // 12: G7: symptom_final; MT=2 (512 CTAs)
    mgemm<ACT_FINAL, A_PRE, OUT_F32, 2, 2><<<dim3(SYM / 128, Bdim / 64), 256, S3_MT2>>>(
        bp + O_H1_H, bp + O_H1_M, nullptr, bp + O_W2_H, bp + O_W2_M,
        b2, symptom_out, nullptr, nullptr,
        Bdim, SYM, HIDD, mu, symtf, sym_flag, symptoms_mask);
}

// round 15
// speedup vs baseline: 1.1327x; 1.0279x over previous
#include <cuda_runtime.h>
#include <cuda_bf16.h>
#include <math.h>
#include <stdint.h>

#define Bdim 8192
#define Edim 4096
#define DEMB 256
#define HIDD 1024
#define DIS 128
#define SYM 512
#define DST 640   // DIS + SYM

enum { ACT_NONE = 0, ACT_RELU = 1, ACT_FSIG = 2, ACT_FINAL = 3 };
enum { OUT_F32 = 0, OUT_SPLIT = 1, OUT_SPLIT_T = 2 };
enum { A_PRE = 0, A_EXACT = 1, A_F32 = 2 };

typedef __nv_bfloat16 bf16;

// ---------------- scratch layout ----------------
constexpr size_t N_ST   = (size_t)Bdim * DEMB;
constexpr size_t N_H1   = (size_t)Bdim * HIDD;
constexpr size_t N_DIS  = (size_t)Bdim * DIS;
constexpr size_t N_SYMM = (size_t)Bdim * SYM;
constexpr size_t N_STU  = (size_t)Bdim * DST;
constexpr size_t N_WG   = (size_t)Edim * DEMB;
constexpr size_t N_GR   = (size_t)Edim * DEMB;
constexpr size_t N_WD1  = (size_t)SYM * DIS;
constexpr size_t N_W1   = (size_t)DEMB * HIDD;
constexpr size_t N_W2   = (size_t)HIDD * SYM;
constexpr size_t N_WM1  = (size_t)DST * HIDD;
constexpr size_t N_MD   = (size_t)DIS * SYM;

constexpr size_t O_ST_H  = 0;
constexpr size_t O_ST_M  = O_ST_H  + N_ST;
constexpr size_t O_H1_H  = O_ST_M  + N_ST;
constexpr size_t O_H1_M  = O_H1_H  + N_H1;
constexpr size_t O_DIS_H = O_H1_M  + N_H1;
constexpr size_t O_DIS_M = O_DIS_H + N_DIS;
constexpr size_t O_SYMM  = O_DIS_M + N_DIS;
constexpr size_t O_STU   = O_SYMM  + N_SYMM;
constexpr size_t O_WG_H  = O_STU   + N_STU;
constexpr size_t O_WG_M  = O_WG_H  + N_WG;
constexpr size_t O_GR_H  = O_WG_M  + N_WG;
constexpr size_t O_GR_M  = O_GR_H  + N_GR;
constexpr size_t O_WD1_H = O_GR_M  + N_GR;
constexpr size_t O_WD1_M = O_WD1_H + N_WD1;
constexpr size_t O_W1_H  = O_WD1_M + N_WD1;
constexpr size_t O_W1_M  = O_W1_H  + N_W1;
constexpr size_t O_W2_H  = O_W1_M  + N_W1;
constexpr size_t O_W2_M  = O_W2_H  + N_W2;
constexpr size_t O_WM1_H = O_W2_M  + N_W2;
constexpr size_t O_WM1_M = O_WM1_H + N_WM1;
constexpr size_t O_MD_H  = O_WM1_M + N_WM1;
constexpr size_t O_MD_M  = O_MD_H  + N_MD;
constexpr size_t BF_TOTAL = O_MD_M + N_MD;

constexpr size_t F_HM    = 0;
constexpr size_t F_SYMTF = F_HM + (size_t)Bdim * HIDD;
constexpr size_t F_MU    = F_SYMTF + (size_t)Bdim * SYM;
constexpr size_t F_DLOG  = F_MU + Bdim;
constexpr size_t F_P2    = F_DLOG + (size_t)Bdim * DIS;      // G2 partials: 2 x B x DEMB
constexpr size_t F_P1    = F_P2 + 2 * (size_t)Bdim * DEMB;   // G1 partials: 2 x E x DEMB
constexpr size_t F_TOTAL = F_P1 + 2 * (size_t)Edim * DEMB;

__device__ __align__(16) bf16  g_bf[BF_TOTAL];
__device__ __align__(16) float g_f32[F_TOTAL];

// ---------------- PTX helpers (sm_80-era only) ----------------
__device__ __forceinline__ uint32_t smem_u32(const void* p) {
    uint32_t a;
    asm("{ .reg .u64 t; cvta.to.shared.u64 t, %1; cvt.u32.u64 %0, t; }"
        : "=r"(a) : "l"(p));
    return a;
}
__device__ __forceinline__ void cpasync16(uint32_t dst, const void* src) {
    asm volatile("cp.async.cg.shared.global [%0], [%1], 16;" :: "r"(dst), "l"(src));
}
__device__ __forceinline__ void ldmat_x4(uint32_t* r, uint32_t addr) {
    asm volatile("ldmatrix.sync.aligned.m8n8.x4.shared.b16 {%0,%1,%2,%3}, [%4];"
                 : "=r"(r[0]), "=r"(r[1]), "=r"(r[2]), "=r"(r[3]) : "r"(addr));
}
__device__ __forceinline__ void mma16816(float* d, const uint32_t* a,
                                         uint32_t b0, uint32_t b1) {
    asm volatile("mma.sync.aligned.m16n8k16.row.col.f32.bf16.bf16.f32 "
                 "{%0,%1,%2,%3}, {%4,%5,%6,%7}, {%8,%9}, {%0,%1,%2,%3};"
                 : "+f"(d[0]), "+f"(d[1]), "+f"(d[2]), "+f"(d[3])
                 : "r"(a[0]), "r"(a[1]), "r"(a[2]), "r"(a[3]), "r"(b0), "r"(b1));
}

// ---------------- mma.sync GEMM (3-stage cp.async, optional split-K) -------
// C[M,N] = act(A @ B + bias); A[M][ld], B as BT[N][ld], bf16 hi/mid split.
// K = k-extent for THIS z-slice; blockIdx.z selects slice (offset z*K).
// BM = 32*MT, BN = 128. BK=32. 256 thr, 8 warps (2M x 4N).
#define BTILE_B 10240           // 128 rows * 80 B (64B data + 16B pad)

template <int ACT, int AMODE, int OMODE, int MT, int MINB>
__global__ __launch_bounds__(256, MINB) void mgemm(
    const bf16* __restrict__ Ah, const bf16* __restrict__ Am,
    const float* __restrict__ Af,
    const bf16* __restrict__ BhT, const bf16* __restrict__ BmT,
    const float* __restrict__ bias, float* __restrict__ C,
    bf16* __restrict__ Ch, bf16* __restrict__ Cm,
    int M, int N, int K, int ld,
    const float* __restrict__ mu, const float* __restrict__ symtf,
    const int* __restrict__ sflag, const int* __restrict__ smask) {
    constexpr int BM = 32 * MT;
    constexpr int A_T = BM * 80;
    constexpr int STAGE = 2 * A_T + 2 * BTILE_B;
    constexpr int NV = (BM * 8 + 255) / 256;
    constexpr int AI = (BM * 4 + 255) / 256;

    extern __shared__ __align__(128) char smem[];
    uint32_t sb = smem_u32(smem);
    int tid = threadIdx.x, wid = tid >> 5, lane = tid & 31;
    int bx = blockIdx.x, by = blockIdx.y, bz = blockIdx.z;
    int wm = wid & 1, wn = wid >> 1;
    size_t kofs = (size_t)bz * K;

    const bf16* pa_h = (AMODE == A_F32) ? nullptr : Ah + (size_t)by * BM * ld + kofs;
    const bf16* pa_m = (AMODE == A_PRE) ? Am + (size_t)by * BM * ld + kofs : pa_h;
    const float* paf = (AMODE == A_F32) ? Af + (size_t)by * BM * ld + kofs : nullptr;
    const bf16* pb_h = BhT + (size_t)bx * 128 * ld + kofs;
    const bf16* pb_m = BmT + (size_t)bx * 128 * ld + kofs;
    float* Cz = C ? C + (size_t)bz * M * N : nullptr;
    int nc = K / 32;

    float acc[MT][4][4];
#pragma unroll
    for (int i = 0; i < MT; i++)
#pragma unroll
        for (int j = 0; j < 4; j++)
#pragma unroll
            for (int q = 0; q < 4; q++) acc[i][j][q] = 0.0f;

    auto copyB = [&](uint32_t base, int k0) {
#pragma unroll
        for (int h = 0; h < 2; h++) {
            int c = tid + h * 256;
            int row = c >> 2, seg = c & 3;
            uint32_t off = (uint32_t)row * 80u + (uint32_t)seg * 16u;
            size_t g = (size_t)row * ld + k0 + seg * 8;
            cpasync16(base + 2 * A_T + off, pb_h + g);
            cpasync16(base + 2 * A_T + BTILE_B + off, pb_m + g);
        }
    };
    auto copyA_pre = [&](uint32_t base, int k0) {
#pragma unroll
        for (int h = 0; h < AI; h++) {
            int c = tid + h * 256;
            if (BM * 4 % 256 != 0 && c >= BM * 4) continue;
            int row = c >> 2, seg = c & 3;
            uint32_t off = (uint32_t)row * 80u + (uint32_t)seg * 16u;
            size_t g = (size_t)row * ld + k0 + seg * 8;
            cpasync16(base + off, pa_h + g);
            if (AMODE == A_PRE) cpasync16(base + A_T + off, pa_m + g);
        }
    };
    auto stsA_f32 = [&](char* cbase, const float4* v) {
#pragma unroll
        for (int i = 0; i < NV; i++) {
            int idx = tid + i * 256;
            if (BM * 8 % 256 != 0 && idx >= BM * 8) continue;
            int row = idx >> 3, c4 = idx & 7;
            char* d = cbase + row * 80 + c4 * 8;
            bf16 h0 = __float2bfloat16(v[i].x), h1 = __float2bfloat16(v[i].y);
            bf16 h2 = __float2bfloat16(v[i].z), h3 = __float2bfloat16(v[i].w);
            *(__nv_bfloat162*)(d)     = __halves2bfloat162(h0, h1);
            *(__nv_bfloat162*)(d + 4) = __halves2bfloat162(h2, h3);
            char* dm = d + A_T;
            *(__nv_bfloat162*)(dm)     = __halves2bfloat162(
                __float2bfloat16(v[i].x - __bfloat162float(h0)),
                __float2bfloat16(v[i].y - __bfloat162float(h1)));
            *(__nv_bfloat162*)(dm + 4) = __halves2bfloat162(
                __float2bfloat16(v[i].z - __bfloat162float(h2)),
                __float2bfloat16(v[i].w - __bfloat162float(h3)));
        }
    };
    auto ldgA_f32 = [&](float4* v, int k0) {
#pragma unroll
        for (int i = 0; i < NV; i++) {
            int idx = tid + i * 256;
            if (BM * 8 % 256 != 0 && idx >= BM * 8) continue;
            int row = idx >> 3, c4 = idx & 7;
            v[i] = *(const float4*)(paf + (size_t)row * ld + k0 + c4 * 4);
        }
    };

    // ---- prologue: preload chunks 0 and 1 ----
    if (AMODE == A_F32) {
        float4 v0[NV];
        ldgA_f32(v0, 0);  stsA_f32(smem, v0);
    } else {
        copyA_pre(sb, 0);
    }
    copyB(sb, 0);
    asm volatile("cp.async.commit_group;" ::: "memory");
    if (AMODE == A_F32) {
        float4 v1[NV];
        ldgA_f32(v1, 32); stsA_f32(smem + STAGE, v1);
    } else {
        copyA_pre(sb + STAGE, 32);
    }
    copyB(sb + STAGE, 32);
    asm volatile("cp.async.commit_group;" ::: "memory");

    // ---- main loop: 3-stage ----
    int scur = 0;
    for (int k = 0; k < nc; k++) {
        if (k + 1 < nc) asm volatile("cp.async.wait_group 1;" ::: "memory");
        else            asm volatile("cp.async.wait_group 0;" ::: "memory");
        __syncthreads();

        bool pre = (k + 2 < nc);
        int spre = scur + 2; if (spre >= 3) spre -= 3;
        float4 afv[NV];
        if (pre && AMODE == A_F32) ldgA_f32(afv, (k + 2) * 32);

        uint32_t sbase = sb + scur * STAGE;
        uint32_t sA_h = sbase;
        uint32_t sA_m = sbase + A_T;
        uint32_t sB_h = sbase + 2 * A_T;
        uint32_t sB_m = sbase + 2 * A_T + BTILE_B;
#pragma unroll
        for (int kk = 0; kk < 2; kk++) {
            uint32_t kb = kk * 32;
            uint32_t afr[MT][4], bfr[2][4];
            auto ldA = [&](uint32_t aB) {
#pragma unroll
                for (int mt = 0; mt < MT; mt++)
                    ldmat_x4(afr[mt],
                             aB + (uint32_t)(wm * (16 * MT) + mt * 16 + (lane & 15)) * 80
                                + kb + (uint32_t)(lane >> 4) * 16);
            };
            auto ldB = [&](uint32_t bB) {
#pragma unroll
                for (int pr = 0; pr < 2; pr++)
                    ldmat_x4(bfr[pr],
                             bB + (uint32_t)(wn * 32 + pr * 16 + (lane & 15)) * 80
                                + kb + (uint32_t)(lane >> 4) * 16);
            };
            auto domma = [&]() {
#pragma unroll
                for (int mt = 0; mt < MT; mt++)
#pragma unroll
                    for (int nt = 0; nt < 4; nt++)
                        mma16816(acc[mt][nt], afr[mt],
                                 bfr[nt >> 1][nt & 1], bfr[nt >> 1][(nt & 1) + 2]);
            };
            ldA(sA_h); ldB(sB_h); domma();
            ldB(sB_m); domma();
            if (AMODE != A_EXACT) {
                ldA(sA_m); ldB(sB_h); domma();
            }
        }

        if (pre) {
            uint32_t sbase_n = sb + spre * STAGE;
            char* cbase_n = smem + spre * STAGE;
            if (AMODE == A_F32) stsA_f32(cbase_n, afv);
            else copyA_pre(sbase_n, (k + 2) * 32);
            copyB(sbase_n, (k + 2) * 32);
            asm volatile("cp.async.commit_group;" ::: "memory");
        }
        scur = (scur + 1 == 3) ? 0 : scur + 1;
    }

    // ---------------- epilogue ----------------
#pragma unroll
    for (int mt = 0; mt < MT; mt++) {
#pragma unroll
        for (int nt = 0; nt < 4; nt++) {
#pragma unroll
            for (int i2 = 0; i2 < 2; i2++) {
                int row = by * BM + wm * (16 * MT) + mt * 16 + (lane >> 2) + i2 * 8;
                int col = bx * 128 + wn * 32 + nt * 8 + (lane & 3) * 2;
                float v0 = acc[mt][nt][i2 * 2 + 0];
                float v1 = acc[mt][nt][i2 * 2 + 1];
                if (bias) { v0 += bias[col]; v1 += bias[col + 1]; }
                if (ACT == ACT_RELU) {
                    v0 = fmaxf(v0, 0.0f); v1 = fmaxf(v1, 0.0f);
                } else if (ACT == ACT_FSIG) {
                    v0 = (v0 > 0.0f) ? 1.0f / (1.0f + expf(-v0)) : v0;
                    v1 = (v1 > 0.0f) ? 1.0f / (1.0f + expf(-v1)) : v1;
                } else if (ACT == ACT_FINAL) {
                    float m = mu[row];
                    size_t o = (size_t)row * SYM + col;
                    float p0 = 1.0f / (1.0f + expf(-v0));
                    float p1 = 1.0f / (1.0f + expf(-v1));
                    v0 = (m * p0 + (1.0f - m) * symtf[o]) *
                         (float)sflag[o] * (float)smask[o];
                    v1 = (m * p1 + (1.0f - m) * symtf[o + 1]) *
                         (float)sflag[o + 1] * (float)smask[o + 1];
                }
                if (OMODE == OUT_F32) {
                    *(float2*)(Cz + (size_t)row * N + col) = make_float2(v0, v1);
                } else if (OMODE == OUT_SPLIT) {
                    bf16 h0 = __float2bfloat16(v0), h1 = __float2bfloat16(v1);
                    size_t o = (size_t)row * N + col;
                    *(__nv_bfloat162*)(Ch + o) = __halves2bfloat162(h0, h1);
                    *(__nv_bfloat162*)(Cm + o) = __halves2bfloat162(
                        __float2bfloat16(v0 - __bfloat162float(h0)),
                        __float2bfloat16(v1 - __bfloat162float(h1)));
                } else {  // OUT_SPLIT_T
                    bf16 h0 = __float2bfloat16(v0), h1 = __float2bfloat16(v1);
                    Ch[(size_t)col * M + row] = h0;
                    Ch[(size_t)(col + 1) * M + row] = h1;
                    Cm[(size_t)col * M + row] =
                        __float2bfloat16(v0 - __bfloat162float(h0));
                    Cm[(size_t)(col + 1) * M + row] =
                        __float2bfloat16(v1 - __bfloat162float(h1));
                }
            }
        }
    }
}

// ---------------- reduce kernels for split-K ----------------
// p0/p1 fp32 partials [n]; out = bf16 split of (p0+p1). n % 4 == 0.
__global__ void reduce_split_kernel(const float* __restrict__ p,
                                    bf16* __restrict__ oh, bf16* __restrict__ om,
                                    int n4) {
    int i = blockIdx.x * blockDim.x + threadIdx.x;
    if (i >= n4) return;
    size_t n = (size_t)n4 * 4;
    float4 a = ((const float4*)p)[i];
    float4 b = ((const float4*)(p + n))[i];
    float v0 = a.x + b.x, v1 = a.y + b.y, v2 = a.z + b.z, v3 = a.w + b.w;
    bf16 h0 = __float2bfloat16(v0), h1 = __float2bfloat16(v1);
    bf16 h2 = __float2bfloat16(v2), h3 = __float2bfloat16(v3);
    ((__nv_bfloat162*)oh)[i * 2]     = __halves2bfloat162(h0, h1);
    ((__nv_bfloat162*)oh)[i * 2 + 1] = __halves2bfloat162(h2, h3);
    ((__nv_bfloat162*)om)[i * 2]     = __halves2bfloat162(
        __float2bfloat16(v0 - __bfloat162float(h0)),
        __float2bfloat16(v1 - __bfloat162float(h1)));
    ((__nv_bfloat162*)om)[i * 2 + 1] = __halves2bfloat162(
        __float2bfloat16(v2 - __bfloat162float(h2)),
        __float2bfloat16(v3 - __bfloat162float(h3)));
}

// partials [Mr][Nc] x2 -> relu(p0+p1) transposed split: out [Nc][Mr].
__global__ void reduceT_relu_kernel(const float* __restrict__ p,
                                    bf16* __restrict__ hiT, bf16* __restrict__ midT,
                                    int Mr, int Nc) {
    __shared__ float t[32][33];
    int tx = threadIdx.x, ty = threadIdx.y;
    int n0 = blockIdx.x * 32, m0 = blockIdx.y * 32;
    size_t sz = (size_t)Mr * Nc;
#pragma unroll
    for (int j = ty; j < 32; j += 8) {
        size_t o = (size_t)(m0 + j) * Nc + n0 + tx;
        t[j][tx] = p[o] + p[o + sz];
    }
    __syncthreads();
#pragma unroll
    for (int j = ty; j < 32; j += 8) {
        float v = fmaxf(t[tx][j], 0.0f);
        bf16 h = __float2bfloat16(v);
        size_t o = (size_t)(n0 + j) * Mr + m0 + tx;
        hiT[o] = h;
        midT[o] = __float2bfloat16(v - __bfloat162float(h));
    }
}

// ---------------- prep / split kernels ----------------
__global__ void prep_kernel(const int* __restrict__ dialog_state,
                            const int* __restrict__ sym_mask,
                            bf16* __restrict__ state_bf,
                            bf16* __restrict__ symmask_bf) {
    int i = blockIdx.x * blockDim.x + threadIdx.x;
    if (i < Bdim * DST) {
        int v = dialog_state[i];
        state_bf[i] = __float2bfloat16((v == 1) ? 1.0f : ((v == -1) ? -1.0f : 0.0f));
    }
    if (i < Bdim * SYM) symmask_bf[i] = __float2bfloat16((float)sym_mask[i]);
}

__device__ __forceinline__ void splitT_tile(const float* __restrict__ in,
                                            bf16* __restrict__ hiT,
                                            bf16* __restrict__ midT,
                                            int K, int N, int n0, int k0,
                                            float (*t)[33]) {
    int tx = threadIdx.x, ty = threadIdx.y;
#pragma unroll
    for (int j = ty; j < 32; j += 8)
        t[j][tx] = in[(size_t)(k0 + j) * N + n0 + tx];
    __syncthreads();
#pragma unroll
    for (int j = ty; j < 32; j += 8) {
        float v = t[tx][j];
        bf16 h = __float2bfloat16(v);
        size_t o = (size_t)(n0 + j) * K + k0 + tx;
        hiT[o] = h;
        midT[o] = __float2bfloat16(v - __bfloat162float(h));
    }
}

__global__ void splitT_kernel(const float* __restrict__ in,
                              bf16* __restrict__ hiT, bf16* __restrict__ midT,
                              int K, int N) {
    __shared__ float t[32][33];
    splitT_tile(in, hiT, midT, K, N, blockIdx.x * 32, blockIdx.y * 32, t);
}

__global__ void splitT_batch(const float* __restrict__ Wd1,
                             const float* __restrict__ W1,
                             const float* __restrict__ W2,
                             const float* __restrict__ Wm1,
                             const float* __restrict__ m_d,
                             bf16* __restrict__ bp) {
    __shared__ float t[32][33];
    int b = blockIdx.x;
    const float* in; bf16 *hiT, *midT; int K, N, tile;
    if (b < 64)        { in = Wd1; hiT = bp + O_WD1_H; midT = bp + O_WD1_M; K = SYM;  N = DIS;  tile = b; }
    else if (b < 320)  { in = W1;  hiT = bp + O_W1_H;  midT = bp + O_W1_M;  K = DEMB; N = HIDD; tile = b - 64; }
    else if (b < 832)  { in = W2;  hiT = bp + O_W2_H;  midT = bp + O_W2_M;  K = HIDD; N = SYM;  tile = b - 320; }
    else if (b < 1472) { in = Wm1; hiT = bp + O_WM1_H; midT = bp + O_WM1_M; K = DST;  N = HIDD; tile = b - 832; }
    else               { in = m_d; hiT = bp + O_MD_H;  midT = bp + O_MD_M;  K = DIS;  N = SYM;  tile = b - 1472; }
    int ntx = N / 32;
    splitT_tile(in, hiT, midT, K, N, (tile % ntx) * 32, (tile / ntx) * 32, t);
}

__global__ void softmax_mask_kernel(const float* __restrict__ logits,
                                    const int* __restrict__ dmask,
                                    float* __restrict__ out,
                                    bf16* __restrict__ oh, bf16* __restrict__ om) {
    int gw = (blockIdx.x * blockDim.x + threadIdx.x) >> 5;
    int lane = threadIdx.x & 31;
    if (gw >= Bdim) return;
    const float* row = logits + (size_t)gw * DIS;
    float v0 = row[lane], v1 = row[lane + 32], v2 = row[lane + 64], v3 = row[lane + 96];
    float mx = fmaxf(fmaxf(v0, v1), fmaxf(v2, v3));
#pragma unroll
    for (int o = 16; o; o >>= 1) mx = fmaxf(mx, __shfl_xor_sync(0xffffffffu, mx, o));
    v0 = expf(v0 - mx); v1 = expf(v1 - mx); v2 = expf(v2 - mx); v3 = expf(v3 - mx);
    float s = v0 + v1 + v2 + v3;
#pragma unroll
    for (int o = 16; o; o >>= 1) s += __shfl_xor_sync(0xffffffffu, s, o);
    float inv = 1.0f / s;
    const int* dm = dmask + (size_t)gw * DIS;
    size_t base = (size_t)gw * DIS;
#pragma unroll
    for (int q = 0; q < 4; q++) {
        float v = (q == 0 ? v0 : q == 1 ? v1 : q == 2 ? v2 : v3) * inv *
                  (float)dm[lane + q * 32];
        size_t o = base + lane + q * 32;
        out[o] = v;
        bf16 h = __float2bfloat16(v);
        oh[o] = h;
        om[o] = __float2bfloat16(v - __bfloat162float(h));
    }
}

__global__ void mu_kernel(const float* __restrict__ hm,
                          const float* __restrict__ Wm2,
                          const float* __restrict__ bm2,
                          float* __restrict__ mu) {
    int gw = (blockIdx.x * blockDim.x + threadIdx.x) >> 5;
    int lane = threadIdx.x & 31;
    if (gw >= Bdim) return;
    const float* row = hm + (size_t)gw * HIDD;
    float s = 0.0f;
#pragma unroll
    for (int j = 0; j < HIDD / 32; j++)
        s = fmaf(row[lane + 32 * j], Wm2[lane + 32 * j], s);
#pragma unroll
    for (int o = 16; o; o >>= 1) s += __shfl_xor_sync(0xffffffffu, s, o);
    if (lane == 0) mu[gw] = 1.0f / (1.0f + expf(-(s + bm2[0])));
}

// ---------------- launch ----------------
#define S3_MT2 (3 * (2 * 64 * 80 + 2 * BTILE_B))   // 92160
#define S3_MT1 (3 * (2 * 32 * 80 + 2 * BTILE_B))   // 76800

extern "C" void kernel_launch(void* const* d_in, const int* in_sizes, int n_in,
                              void* d_out, int out_size) {
    const int*   dialog_state  = (const int*)d_in[0];
    const float* dsr           = (const float*)d_in[1];
    const float* kg_adj        = (const float*)d_in[2];
    const int*   sym_flag      = (const int*)d_in[3];
    const int*   sym_mask      = (const int*)d_in[4];
    const int*   disease_mask  = (const int*)d_in[5];
    const int*   symptoms_mask = (const int*)d_in[6];
    const float* W_g  = (const float*)d_in[7];
    const float* Wd1  = (const float*)d_in[8];
    const float* bd1  = (const float*)d_in[9];
    const float* W1   = (const float*)d_in[10];
    const float* b1   = (const float*)d_in[11];
    const float* W2   = (const float*)d_in[12];
    const float* b2   = (const float*)d_in[13];
    const float* Wm1  = (const float*)d_in[14];
    const float* bm1  = (const float*)d_in[15];
    const float* Wm2  = (const float*)d_in[16];
    const float* bm2  = (const float*)d_in[17];
    const float* m_d  = (const float*)d_in[18];

    float* out = (float*)d_out;
    float* disease_out = out;
    float* symptom_out = out + (size_t)Bdim * DIS;

    bf16* bp = nullptr;  float* fp = nullptr;
    cudaGetSymbolAddress((void**)&bp, g_bf);
    cudaGetSymbolAddress((void**)&fp, g_f32);

    float* hm      = fp + F_HM;
    float* symtf   = fp + F_SYMTF;
    float* mu      = fp + F_MU;
    float* dlogits = fp + F_DLOG;
    float* p2      = fp + F_P2;
    float* p1      = fp + F_P1;

    cudaFuncSetAttribute(mgemm<ACT_NONE, A_F32, OUT_F32, 2, 2>,     cudaFuncAttributeMaxDynamicSharedMemorySize, S3_MT2);
    cudaFuncSetAttribute(mgemm<ACT_NONE, A_EXACT, OUT_F32, 1, 2>,   cudaFuncAttributeMaxDynamicSharedMemorySize, S3_MT1);
    cudaFuncSetAttribute(mgemm<ACT_FSIG, A_PRE, OUT_F32, 2, 2>,     cudaFuncAttributeMaxDynamicSharedMemorySize, S3_MT2);
    cudaFuncSetAttribute(mgemm<ACT_RELU, A_PRE, OUT_SPLIT, 2, 2>,   cudaFuncAttributeMaxDynamicSharedMemorySize, S3_MT2);
    cudaFuncSetAttribute(mgemm<ACT_RELU, A_EXACT, OUT_F32, 2, 2>,   cudaFuncAttributeMaxDynamicSharedMemorySize, S3_MT2);
    cudaFuncSetAttribute(mgemm<ACT_FINAL, A_PRE, OUT_F32, 2, 2>,    cudaFuncAttributeMaxDynamicSharedMemorySize, S3_MT2);

    // 1: prep
    prep_kernel<<<(Bdim * DST + 255) / 256, 256>>>(dialog_state, sym_mask,
                                                   bp + O_STU, bp + O_SYMM);
    // 2: split W_g
    dim3 tb(32, 8);
    splitT_kernel<<<dim3(DEMB / 32, Edim / 32), tb>>>(W_g, bp + O_WG_H, bp + O_WG_M, Edim, DEMB);

    // 3: split remaining weights (one launch)
    splitT_batch<<<1536, tb>>>(Wd1, W1, W2, Wm1, m_d, bp);

    // 4: G1 partials: kg_adj @ W_g, split-K=2, MT=2 (grid 2x64x2 = 256 CTAs)
    //    (ncu -s 5 profiles this launch)
    mgemm<ACT_NONE, A_F32, OUT_F32, 2, 2><<<dim3(DEMB / 128, Edim / 64, 2), 256, S3_MT2>>>(
        nullptr, nullptr, kg_adj, bp + O_WG_H, bp + O_WG_M,
        nullptr, p1, nullptr, nullptr,
        Edim, DEMB, Edim / 2, Edim, nullptr, nullptr, nullptr, nullptr);

    // 5: reduce G1 -> relu -> graph_rep^T split
    reduceT_relu_kernel<<<dim3(DEMB / 32, Edim / 32), tb>>>(p1, bp + O_GR_H, bp + O_GR_M,
                                                            Edim, DEMB);

    // 6: G2 partials: dsr @ graph_rep, split-K=2, MT=2 (grid 2x128x2 = 512 CTAs)
    mgemm<ACT_NONE, A_F32, OUT_F32, 2, 2><<<dim3(DEMB / 128, Bdim / 64, 2), 256, S3_MT2>>>(
        nullptr, nullptr, dsr, bp + O_GR_H, bp + O_GR_M,
        nullptr, p2, nullptr, nullptr,
        Bdim, DEMB, Edim / 2, Edim, nullptr, nullptr, nullptr, nullptr);

    // 7: reduce G2 -> state split
    reduce_split_kernel<<<(int)((N_ST / 4 + 255) / 256), 256>>>(p2, bp + O_ST_H, bp + O_ST_M,
                                                                (int)(N_ST / 4));

    // 8: G3: dlogits = sym_mask @ Wd1 + bd1 (A exact); MT=1 (256 CTAs)
    mgemm<ACT_NONE, A_EXACT, OUT_F32, 1, 2><<<dim3(DIS / 128, Bdim / 32), 256, S3_MT1>>>(
        bp + O_SYMM, nullptr, nullptr, bp + O_WD1_H, bp + O_WD1_M,
        bd1, dlogits, nullptr, nullptr,
        Bdim, DIS, SYM, SYM, nullptr, nullptr, nullptr, nullptr);

    // 9: softmax
    softmax_mask_kernel<<<Bdim / 8, 256>>>(dlogits, disease_mask, disease_out,
                                           bp + O_DIS_H, bp + O_DIS_M);

    // 10: G4: symtf = filter_sig(disease @ m_d); MT=2 (512 CTAs)
    mgemm<ACT_FSIG, A_PRE, OUT_F32, 2, 2><<<dim3(SYM / 128, Bdim / 64), 256, S3_MT2>>>(
        bp + O_DIS_H, bp + O_DIS_M, nullptr, bp + O_MD_H, bp + O_MD_M,
        nullptr, symtf, nullptr, nullptr,
        Bdim, SYM, DIS, DIS, nullptr, nullptr, nullptr, nullptr);

    // 11: G5: h1 = relu(state @ W1 + b1) -> split; MT=2 (1024 CTAs)
    mgemm<ACT_RELU, A_PRE, OUT_SPLIT, 2, 2><<<dim3(HIDD / 128, Bdim / 64), 256, S3_MT2>>>(
        bp + O_ST_H, bp + O_ST_M, nullptr, bp + O_W1_H, bp + O_W1_M,
        b1, nullptr, bp + O_H1_H, bp + O_H1_M,
        Bdim, HIDD, DEMB, DEMB, nullptr, nullptr, nullptr, nullptr);

    // 12: G6: hm = relu(state_ @ Wm1 + bm1) (A exact); MT=2 (1024 CTAs)
    mgemm<ACT_RELU, A_EXACT, OUT_F32, 2, 2><<<dim3(HIDD / 128, Bdim / 64), 256, S3_MT2>>>(
        bp + O_STU, nullptr, nullptr, bp + O_WM1_H, bp + O_WM1_M,
        bm1, hm, nullptr, nullptr,
        Bdim, HIDD, DST, DST, nullptr, nullptr, nullptr, nullptr);

    // 13: mu
    mu_kernel<<<Bdim / 8, 256>>>(hm, Wm2, bm2, mu);

    // 14: G7: symptom_final; MT=2 (512 CTAs)
    mgemm<ACT_FINAL, A_PRE, OUT_F32, 2, 2><<<dim3(SYM / 128, Bdim / 64), 256, S3_MT2>>>(
        bp + O_H1_H, bp + O_H1_M, nullptr, bp + O_W2_H, bp + O_W2_M,
        b2, symptom_out, nullptr, nullptr,
        Bdim, SYM, HIDD, HIDD, mu, symtf, sym_flag, symptoms_mask);
}